// round 5
// baseline (speedup 1.0000x reference)
#include <cuda_runtime.h>
#include <cuda_fp16.h>
#include <mma.h>
#include <cstdint>

using namespace nvcuda;

// ---------------- problem constants ----------------
#define B_   4
#define T_   4096
#define DIN  1024
#define H_   16
#define D_   64
#define NCOL 2048            // H*D*2
#define BT   (B_*T_)         // 16384
#define BH   (B_*H_)         // 64
#define CH   128
#define NC   (T_/CH)         // 32

// ---------------- GEMM tile config ----------------
#define MT   128             // rows per CTA (= one scan chunk)
#define NTILE 256            // cols per CTA = two heads
#define KC   64              // k per stage
#define NSTG (DIN/KC)        // 16
#define PAD  24
#define LDS_ (KC + PAD)      // 88 halves = 176B rows
#define TILE_A_BYTES (MT * LDS_ * 2)        // 22528
#define TILE_W_BYTES (NTILE * LDS_ * 2)     // 45056
#define STAGE_BYTES (TILE_A_BYTES + TILE_W_BYTES)  // 67584
#define SM_Q_OFF   (2 * STAGE_BYTES)        // 135168
#define SM_PEU_OFF (SM_Q_OFF + 512)         // 135680
#define SMEM_TOTAL (SM_PEU_OFF + 1024)      // 136704
#define CLD2 260             // epilogue C row stride (floats); 128*260*4 = 133120 <= 135168

// ---------------- device scratch ----------------
__device__ __half g_Ah[BT * DIN];
__device__ __half g_Wt[NCOL * DIN];   // transposed: [n][k]
__device__ float g_ev[BH * T_ * D_];
__device__ float g_eu[BH * T_];
__device__ float g_csev[BH * NC * D_];
__device__ float g_cseu[BH * NC];

// ---------------- helpers ----------------
__device__ __forceinline__ uint32_t smem_u32(const void* p) {
    uint32_t a;
    asm("{ .reg .u64 t; cvta.to.shared.u64 t, %1; cvt.u32.u64 %0, t; }" : "=r"(a) : "l"(p));
    return a;
}
#define CP_ASYNC16(dst, src) \
    asm volatile("cp.async.ca.shared.global [%0], [%1], 16;" :: "r"(dst), "l"(src))
#define CP_COMMIT() asm volatile("cp.async.commit_group;" ::: "memory")
#define CP_WAIT1()  asm volatile("cp.async.wait_group 1;" ::: "memory")
#define CP_WAIT0()  asm volatile("cp.async.wait_group 0;" ::: "memory")

// ---------------------------------------------------------------------------
// K0a: convert A (f32) -> fp16
// ---------------------------------------------------------------------------
__global__ void k0_convA(const float* __restrict__ A) {
    int i = (blockIdx.x * 256 + threadIdx.x) * 4;
    float4 v = *(const float4*)(A + i);
    __half2* o = (__half2*)(g_Ah + i);
    o[0] = __floats2half2_rn(v.x, v.y);
    o[1] = __floats2half2_rn(v.z, v.w);
}

// ---------------------------------------------------------------------------
// K0b: transpose + convert W (f32 [DIN][NCOL]) -> fp16 [NCOL][DIN]
// ---------------------------------------------------------------------------
__global__ void k0_convW(const float* __restrict__ W) {
    __shared__ float tile[32][33];
    int n0 = blockIdx.x * 32, k0 = blockIdx.y * 32;
#pragma unroll
    for (int j = 0; j < 32; j += 8)
        tile[threadIdx.y + j][threadIdx.x] = W[(k0 + threadIdx.y + j) * NCOL + n0 + threadIdx.x];
    __syncthreads();
#pragma unroll
    for (int j = 0; j < 32; j += 8) {
        float x = tile[threadIdx.x][threadIdx.y + j];
        g_Wt[(n0 + threadIdx.y + j) * DIN + k0 + threadIdx.x] = __float2half_rn(x);
    }
}

// ---------------------------------------------------------------------------
// K1: wmma fp16 GEMM (128 rows x 2 heads per CTA) + fused epilogue + chunk sums
// ---------------------------------------------------------------------------
__global__ void __launch_bounds__(512, 1) k1_mma(const float* __restrict__ Q) {
    extern __shared__ char smem[];
    const uint32_t sb = smem_u32(smem);
    const int tid = threadIdx.x;
    const int wid = tid >> 5;
    const int hp = blockIdx.x;            // head pair 0..7
    const int mtile = blockIdx.y;         // 0..127
    const int rowBase = mtile * MT;
    const int nBase = hp * NTILE;

    float* qs = (float*)(smem + SM_Q_OFF);
    if (tid < 128) qs[tid] = Q[hp * 128 + tid];

    // 16 warps: 4(m) x 4(n); warp tile 32(m) x 64(n)
    const int warp_m = wid & 3;
    const int warp_n = wid >> 2;

    wmma::fragment<wmma::accumulator, 16, 16, 16, float> acc[2][4];
#pragma unroll
    for (int i = 0; i < 2; i++)
#pragma unroll
        for (int j = 0; j < 4; j++) wmma::fill_fragment(acc[i][j], 0.f);

    // cp.async: 512 threads = 64 rows x 8 chunks of 16B per rep
    const int r_ = tid >> 3;          // 0..63
    const int c_ = tid & 7;
    auto issue_stage = [&](int sbuf, int k0) {
        const uint32_t stg = sb + sbuf * STAGE_BYTES;
#pragma unroll
        for (int rep = 0; rep < 2; rep++) {           // A: 128 rows
            const int r = r_ + rep * 64;
            const uint32_t so = (uint32_t)((r * LDS_ + c_ * 8) * 2);
            CP_ASYNC16(stg + so, g_Ah + (rowBase + r) * DIN + k0 + c_ * 8);
        }
#pragma unroll
        for (int rep = 0; rep < 4; rep++) {           // W: 256 rows
            const int r = r_ + rep * 64;
            const uint32_t so = (uint32_t)((r * LDS_ + c_ * 8) * 2);
            CP_ASYNC16(stg + TILE_A_BYTES + so, g_Wt + (nBase + r) * DIN + k0 + c_ * 8);
        }
        CP_COMMIT();
    };

    issue_stage(0, 0);
    issue_stage(1, KC);

    for (int it = 0; it < NSTG; it++) {
        if (it >= NSTG - 2) { CP_WAIT0(); } else { CP_WAIT1(); }
        __syncthreads();
        const __half* As = (const __half*)(smem + (it & 1) * STAGE_BYTES);
        const __half* Ws = (const __half*)(smem + (it & 1) * STAGE_BYTES + TILE_A_BYTES);

#pragma unroll
        for (int ks = 0; ks < KC / 16; ks++) {
            wmma::fragment<wmma::matrix_a, 16, 16, 16, __half, wmma::row_major> af[2];
#pragma unroll
            for (int i = 0; i < 2; i++)
                wmma::load_matrix_sync(af[i], As + (warp_m * 32 + i * 16) * LDS_ + ks * 16, LDS_);
#pragma unroll
            for (int jseg = 0; jseg < 2; jseg++) {
                wmma::fragment<wmma::matrix_b, 16, 16, 16, __half, wmma::col_major> bf[2];
#pragma unroll
                for (int jj = 0; jj < 2; jj++)
                    wmma::load_matrix_sync(bf[jj],
                        Ws + (warp_n * 64 + (jseg * 2 + jj) * 16) * LDS_ + ks * 16, LDS_);
#pragma unroll
                for (int i = 0; i < 2; i++)
#pragma unroll
                    for (int jj = 0; jj < 2; jj++)
                        wmma::mma_sync(acc[i][jseg * 2 + jj], af[i], bf[jj], acc[i][jseg * 2 + jj]);
            }
        }
        __syncthreads();
        if (it + 2 < NSTG) issue_stage(it & 1, (it + 2) * KC);
    }
    __syncthreads();   // all mma done before overlaying stage buffers with C

    // ---- store accumulators to smem C [128][CLD2] ----
    float* Cs = (float*)smem;
#pragma unroll
    for (int i = 0; i < 2; i++)
#pragma unroll
        for (int j = 0; j < 4; j++)
            wmma::store_matrix_sync(Cs + (warp_m * 32 + i * 16) * CLD2 + warp_n * 64 + j * 16,
                                    acc[i][j], CLD2, wmma::mem_row_major);
    __syncthreads();

    // ---- fused epilogue: thread = (row, h_local, d-half) ----
    float* peu = (float*)(smem + SM_PEU_OFF);
    {
        const int row = tid >> 2;
        const int q4 = tid & 3;
        const int h_local = q4 >> 1;
        const int dh = q4 & 1;             // d in [dh*32, dh*32+32)
        const int gRow = rowBase + row;
        const int b = gRow >> 12, t = gRow & 4095;
        float* crow = Cs + row * CLD2 + h_local * 128 + dh * 64;
        const float* q = qs + h_local * 64 + dh * 32;

        float sp = 0.f;
        float vv[32];
#pragma unroll
        for (int d = 0; d < 32; d++) {
            float2 kv = *(const float2*)(crow + 2 * d);
            sp = fmaf(q[d], fmaxf(kv.x, 0.f), sp);
            vv[d] = fmaxf(kv.y, 0.f);
        }
        sp += __shfl_xor_sync(0xffffffffu, sp, 1);   // combine the two d-halves
        const float p = __expf(sp);
        const int h = hp * 2 + h_local;
        const int base = (b * H_ + h) * T_ + t;
        if (dh == 0) { g_eu[base] = p; peu[row * 2 + h_local] = p; }
        float4* dst = (float4*)(g_ev + base * 64 + dh * 32);
#pragma unroll
        for (int i = 0; i < 8; i++) {
            dst[i] = make_float4(p * vv[4 * i], p * vv[4 * i + 1],
                                 p * vv[4 * i + 2], p * vv[4 * i + 3]);
        }
        // write p*v back into the v slots for the chunk-sum reduction
#pragma unroll
        for (int d = 0; d < 32; d++) crow[2 * d + 1] = p * vv[d];
    }
    __syncthreads();

    // ---- chunk sums (replaces k2): this CTA's 128 rows ARE chunk c of batch b ----
    {
        const int b = rowBase >> 12;
        const int c = (rowBase >> 7) & (NC - 1);
        if (tid < 128) {
            const int h_local = tid >> 6, d = tid & 63;
            float s = 0.f;
#pragma unroll 8
            for (int r = 0; r < 128; r++)
                s += Cs[r * CLD2 + h_local * 128 + 2 * d + 1];
            const int bh = b * H_ + hp * 2 + h_local;
            g_csev[(bh * NC + c) * 64 + d] = s;
        } else if (tid < 130) {
            const int h_local = tid - 128;
            float s = 0.f;
            for (int r = 0; r < 128; r++) s += peu[r * 2 + h_local];
            g_cseu[(b * H_ + hp * 2 + h_local) * NC + c] = s;
        }
    }
}

// ---------------------------------------------------------------------------
// K3: exclusive prefix over chunk sums
// ---------------------------------------------------------------------------
__global__ void k3_prefix() {
    const int bh = blockIdx.x;
    const int tid = threadIdx.x;
    float run = 0.f;
    for (int c = 0; c < NC; c++) {
        const int i = (bh * NC + c) * 64 + tid;
        float tmp = g_csev[i];
        g_csev[i] = run;
        run += tmp;
    }
    if (tid == 0) {
        float ru = 0.f;
        for (int c = 0; c < NC; c++) {
            float tmp = g_cseu[bh * NC + c];
            g_cseu[bh * NC + c] = ru;
            ru += tmp;
        }
    }
}

// ---------------------------------------------------------------------------
// K45: fused cumsum + divide + head-sum -> out   (block = (b, chunk))
// ---------------------------------------------------------------------------
__global__ void __launch_bounds__(1024) k45(float* __restrict__ out) {
    __shared__ float sred[8 * 16 * 64];   // [t_sub][h][d]  32KB
    const int bid = blockIdx.x;
    const int b = bid >> 5;
    const int c = bid & (NC - 1);
    const int tid = threadIdx.x;
    const int h = tid >> 6;
    const int d = tid & 63;
    const int bh = b * H_ + h;

    float accw = g_csev[(bh * NC + c) * 64 + d];
    float accu = g_cseu[bh * NC + c];
    const float* evp = g_ev + (bh * T_ + c * CH) * 64 + d;
    const float* eup = g_eu + bh * T_ + c * CH;
    float* outp = out + (b * T_ + c * CH) * 64;

    for (int tb = 0; tb < 16; tb++) {
#pragma unroll
        for (int j = 0; j < 8; j++) {
            const int t = tb * 8 + j;
            accu += eup[t];
            accw += evp[t * 64];
            sred[(j * 16 + h) * 64 + d] = __fdividef(accw, accu);
        }
        __syncthreads();
        if (tid < 512) {
            const int ts = tid >> 6, d2 = tid & 63;
            float s = 0.f;
#pragma unroll
            for (int hh = 0; hh < 16; hh++) s += sred[(ts * 16 + hh) * 64 + d2];
            outp[(tb * 8 + ts) * 64 + d2] = s;
        }
        __syncthreads();
    }
}

// ---------------------------------------------------------------------------
extern "C" void kernel_launch(void* const* d_in, const int* in_sizes, int n_in,
                              void* d_out, int out_size) {
    const float* A = (const float*)d_in[0];   // inputs   [4,4096,1024]
    const float* W = (const float*)d_in[1];   // kv_kernel[1024,16,64,2]
    const float* Q = (const float*)d_in[2];   // q_kernel [16,64]
    float* out = (float*)d_out;

    cudaFuncSetAttribute(k1_mma, cudaFuncAttributeMaxDynamicSharedMemorySize, SMEM_TOTAL);

    k0_convA<<<BT * DIN / 1024, 256>>>(A);
    k0_convW<<<dim3(NCOL / 32, DIN / 32), dim3(32, 8)>>>(W);
    k1_mma<<<dim3(H_ / 2, BT / MT), 512, SMEM_TOTAL>>>(Q);
    k3_prefix<<<BH, 64>>>();
    k45<<<B_ * NC, 1024>>>(out);
}

// round 6
// speedup vs baseline: 1.5727x; 1.5727x over previous
#include <cuda_runtime.h>
#include <cuda_fp16.h>
#include <mma.h>
#include <cstdint>

using namespace nvcuda;

// ---------------- problem constants ----------------
#define B_   4
#define T_   4096
#define DIN  1024
#define H_   16
#define D_   64
#define NCOL 2048            // H*D*2
#define BT   (B_*T_)         // 16384
#define BH   (B_*H_)         // 64
#define CH   128
#define NC   (T_/CH)         // 32

// ---------------- GEMM tile config (round-3 proven) ----------------
#define MT   128             // rows per CTA
#define NTILE 128            // cols per CTA = one head
#define KC   64              // k per stage
#define NSTG (DIN/KC)        // 16
#define PAD  24              // row stride = 88 halves = 176B (16B aligned)
#define LDS_ (KC + PAD)      // 88
#define TILE_BYTES (MT * LDS_ * 2)      // 22528
#define STAGE_BYTES (2 * TILE_BYTES)    // A + W = 45056
#define SM_Q_OFF   (2 * STAGE_BYTES)    // 90112
#define SMEM_TOTAL (SM_Q_OFF + 512)     // 90624
#define CLD  132             // epilogue C row stride (floats)

// ---------------- device scratch ----------------
__device__ __half g_Ah[BT * DIN];
__device__ __half g_Wt[NCOL * DIN];   // transposed: [n][k]
__device__ float g_ev[BH * T_ * D_];
__device__ float g_eu[BH * T_];
__device__ float g_csev[BH * NC * D_];   // RAW chunk sums (prefix done in k45)
__device__ float g_cseu[BH * NC];

// ---------------- helpers ----------------
__device__ __forceinline__ uint32_t smem_u32(const void* p) {
    uint32_t a;
    asm("{ .reg .u64 t; cvta.to.shared.u64 t, %1; cvt.u32.u64 %0, t; }" : "=r"(a) : "l"(p));
    return a;
}
#define CP_ASYNC16(dst, src) \
    asm volatile("cp.async.ca.shared.global [%0], [%1], 16;" :: "r"(dst), "l"(src))
#define CP_COMMIT() asm volatile("cp.async.commit_group;" ::: "memory")
#define CP_WAIT1()  asm volatile("cp.async.wait_group 1;" ::: "memory")
#define CP_WAIT0()  asm volatile("cp.async.wait_group 0;" ::: "memory")

// ---------------------------------------------------------------------------
// K0a: convert A (f32) -> fp16
// ---------------------------------------------------------------------------
__global__ void k0_convA(const float* __restrict__ A) {
    int i = (blockIdx.x * 256 + threadIdx.x) * 4;
    float4 v = *(const float4*)(A + i);
    __half2* o = (__half2*)(g_Ah + i);
    o[0] = __floats2half2_rn(v.x, v.y);
    o[1] = __floats2half2_rn(v.z, v.w);
}

// ---------------------------------------------------------------------------
// K0b: transpose + convert W (f32 [DIN][NCOL]) -> fp16 [NCOL][DIN]
// ---------------------------------------------------------------------------
__global__ void k0_convW(const float* __restrict__ W) {
    __shared__ float tile[32][33];
    int n0 = blockIdx.x * 32, k0 = blockIdx.y * 32;
#pragma unroll
    for (int j = 0; j < 32; j += 8)
        tile[threadIdx.y + j][threadIdx.x] = W[(k0 + threadIdx.y + j) * NCOL + n0 + threadIdx.x];
    __syncthreads();
#pragma unroll
    for (int j = 0; j < 32; j += 8) {
        float x = tile[threadIdx.x][threadIdx.y + j];
        g_Wt[(n0 + threadIdx.y + j) * DIN + k0 + threadIdx.x] = __float2half_rn(x);
    }
}

// ---------------------------------------------------------------------------
// K1: wmma fp16 GEMM (128x128 per CTA = 1 head x 128 t-rows) + fused epilogue
//     (exact round-3 version: 256 threads, occ=2)
// ---------------------------------------------------------------------------
__global__ void __launch_bounds__(256, 2) k1_mma(const float* __restrict__ Q) {
    extern __shared__ char smem[];
    const uint32_t sb = smem_u32(smem);
    const int tid = threadIdx.x;
    const int wid = tid >> 5;
    const int h = blockIdx.x;             // head
    const int mtile = blockIdx.y;         // 0..127
    const int rowBase = mtile * MT;
    const int nBase = h * NTILE;

    float* qs = (float*)(smem + SM_Q_OFF);
    if (tid < 64) qs[tid] = Q[h * 64 + tid];

    // warp tile: 64(m) x 32(n); warp_m = wid&1, warp_n = wid>>1
    const int warp_m = wid & 1;
    const int warp_n = wid >> 1;

    wmma::fragment<wmma::accumulator, 16, 16, 16, float> acc[4][2];
#pragma unroll
    for (int i = 0; i < 4; i++)
#pragma unroll
        for (int j = 0; j < 2; j++) wmma::fill_fragment(acc[i][j], 0.f);

    const int r_ = tid >> 3;
    const int c_ = tid & 7;
    auto issue_stage = [&](int sbuf, int k0) {
        const uint32_t stg = sb + sbuf * STAGE_BYTES;
#pragma unroll
        for (int rep = 0; rep < 4; rep++) {
            const int r = r_ + rep * 32;
            const uint32_t so = (uint32_t)((r * LDS_ + c_ * 8) * 2);
            CP_ASYNC16(stg + so, g_Ah + (rowBase + r) * DIN + k0 + c_ * 8);
            CP_ASYNC16(stg + TILE_BYTES + so, g_Wt + (nBase + r) * DIN + k0 + c_ * 8);
        }
        CP_COMMIT();
    };

    issue_stage(0, 0);
    issue_stage(1, KC);

    for (int it = 0; it < NSTG; it++) {
        if (it >= NSTG - 2) { CP_WAIT0(); } else { CP_WAIT1(); }
        __syncthreads();
        const __half* As = (const __half*)(smem + (it & 1) * STAGE_BYTES);
        const __half* Ws = (const __half*)(smem + (it & 1) * STAGE_BYTES + TILE_BYTES);

#pragma unroll
        for (int ks = 0; ks < KC / 16; ks++) {
            wmma::fragment<wmma::matrix_a, 16, 16, 16, __half, wmma::row_major> af[4];
            wmma::fragment<wmma::matrix_b, 16, 16, 16, __half, wmma::col_major> bf[2];
#pragma unroll
            for (int i = 0; i < 4; i++)
                wmma::load_matrix_sync(af[i], As + (warp_m * 64 + i * 16) * LDS_ + ks * 16, LDS_);
#pragma unroll
            for (int j = 0; j < 2; j++)
                wmma::load_matrix_sync(bf[j], Ws + (warp_n * 32 + j * 16) * LDS_ + ks * 16, LDS_);
#pragma unroll
            for (int i = 0; i < 4; i++)
#pragma unroll
                for (int j = 0; j < 2; j++)
                    wmma::mma_sync(acc[i][j], af[i], bf[j], acc[i][j]);
        }
        __syncthreads();
        if (it + 2 < NSTG) issue_stage(it & 1, (it + 2) * KC);
    }

    // ---- store accumulators to smem C [128][CLD] ----
    float* Cs = (float*)smem;
#pragma unroll
    for (int i = 0; i < 4; i++)
#pragma unroll
        for (int j = 0; j < 2; j++)
            wmma::store_matrix_sync(Cs + (warp_m * 64 + i * 16) * CLD + warp_n * 32 + j * 16,
                                    acc[i][j], CLD, wmma::mem_row_major);
    __syncthreads();

    // ---- fused epilogue: thread = (row, d-half) ----
    {
        const int row = tid >> 1;
        const int half = tid & 1;
        const int gRow = rowBase + row;
        const int b = gRow >> 12, t = gRow & 4095;
        const float* crow = Cs + row * CLD + half * 64;
        const float* q = qs + half * 32;

        float sp = 0.f;
        float vv[32];
#pragma unroll
        for (int d = 0; d < 32; d++) {
            float2 kv = *(const float2*)(crow + 2 * d);
            sp = fmaf(q[d], fmaxf(kv.x, 0.f), sp);
            vv[d] = fmaxf(kv.y, 0.f);
        }
        sp += __shfl_xor_sync(0xffffffffu, sp, 1);
        const float p = __expf(sp);
        const int base = (b * H_ + h) * T_ + t;
        if (half == 0) g_eu[base] = p;
        float4* dst = (float4*)(g_ev + base * 64 + half * 32);
#pragma unroll
        for (int i = 0; i < 8; i++)
            dst[i] = make_float4(p * vv[4 * i], p * vv[4 * i + 1],
                                 p * vv[4 * i + 2], p * vv[4 * i + 3]);
    }
}

// ---------------------------------------------------------------------------
// K2: per-chunk RAW sums; 256-thread blocks, 4 chunks/block (occupancy fix)
// ---------------------------------------------------------------------------
__global__ void __launch_bounds__(256) k2_chunksum() {
    __shared__ float sred[4][64];
    const int slice = threadIdx.x >> 6;     // 0..3
    const int tid2  = threadIdx.x & 63;     // d
    const int idx = blockIdx.x * 4 + slice; // bh*NC + c
    const int bh = idx >> 5;
    const int c  = idx & (NC - 1);

    const float* evp = g_ev + (bh * T_ + c * CH) * 64;
    float s = 0.f;
#pragma unroll 8
    for (int t = 0; t < CH; t++) s += evp[t * 64 + tid2];
    g_csev[(bh * NC + c) * 64 + tid2] = s;

    const float* eup = g_eu + bh * T_ + c * CH;
    sred[slice][tid2] = eup[tid2] + eup[tid2 + 64];
    __syncthreads();
    if (tid2 < 32) {
        float v2 = sred[slice][tid2] + sred[slice][tid2 + 32];
#pragma unroll
        for (int o = 16; o; o >>= 1) v2 += __shfl_down_sync(0xffffffffu, v2, o);
        if (tid2 == 0) g_cseu[bh * NC + c] = v2;
    }
}

// ---------------------------------------------------------------------------
// K45: per-block exclusive prefix over chunk sums + cumsum + divide + head-sum
//      block = (b, chunk); 1024 threads = (h, d)
// ---------------------------------------------------------------------------
__global__ void __launch_bounds__(1024) k45(float* __restrict__ out) {
    __shared__ float sred[8 * 16 * 64];   // [t_sub][h][d]  32KB
    const int bid = blockIdx.x;
    const int b = bid >> 5;
    const int c = bid & (NC - 1);
    const int tid = threadIdx.x;
    const int h = tid >> 6;
    const int d = tid & 63;
    const int bh = b * H_ + h;

    // exclusive prefix of raw chunk sums (replaces k3)
    float accw = 0.f, accu = 0.f;
    for (int cp = 0; cp < c; cp++) {
        accw += g_csev[(bh * NC + cp) * 64 + d];
        accu += g_cseu[bh * NC + cp];
    }

    const float* evp = g_ev + (bh * T_ + c * CH) * 64 + d;
    const float* eup = g_eu + bh * T_ + c * CH;
    float* outp = out + (b * T_ + c * CH) * 64;

    for (int tb = 0; tb < 16; tb++) {
#pragma unroll
        for (int j = 0; j < 8; j++) {
            const int t = tb * 8 + j;
            accu += eup[t];
            accw += evp[t * 64];
            sred[(j * 16 + h) * 64 + d] = __fdividef(accw, accu);
        }
        __syncthreads();
        if (tid < 512) {
            const int ts = tid >> 6, d2 = tid & 63;
            float s = 0.f;
#pragma unroll
            for (int hh = 0; hh < 16; hh++) s += sred[(ts * 16 + hh) * 64 + d2];
            outp[(tb * 8 + ts) * 64 + d2] = s;
        }
        __syncthreads();
    }
}

// ---------------------------------------------------------------------------
extern "C" void kernel_launch(void* const* d_in, const int* in_sizes, int n_in,
                              void* d_out, int out_size) {
    const float* A = (const float*)d_in[0];   // inputs   [4,4096,1024]
    const float* W = (const float*)d_in[1];   // kv_kernel[1024,16,64,2]
    const float* Q = (const float*)d_in[2];   // q_kernel [16,64]
    float* out = (float*)d_out;

    cudaFuncSetAttribute(k1_mma, cudaFuncAttributeMaxDynamicSharedMemorySize, SMEM_TOTAL);

    k0_convA<<<BT * DIN / 1024, 256>>>(A);
    k0_convW<<<dim3(NCOL / 32, DIN / 32), dim3(32, 8)>>>(W);
    k1_mma<<<dim3(H_, BT / MT), 256, SMEM_TOTAL>>>(Q);
    k2_chunksum<<<BH * NC / 4, 256>>>();
    k45<<<B_ * NC, 1024>>>(out);
}